// round 1
// baseline (speedup 1.0000x reference)
#include <cuda_runtime.h>
#include <math.h>

// Problem constants
#define KDIM 128
#define BDIM 16
#define LDIM 8192
#define NF   256          // fine grid (oversampling sigma = 2)
#define WIN  8            // spreading window width
#define BETA 18.397f      // ES kernel beta = pi*w*(1-1/(2*sigma))*0.976
#define PI_F 3.14159265358979f

// Scratch (device globals; no cudaMalloc allowed)
__device__ float d_ctab[256];                 // combined deconv+IDFT table, includes 1/K factor
__device__ float d_corner[BDIM];              // F[64,64] per batch
__device__ float d_g[BDIM * KDIM * NF];       // stage-1 intermediate (b, m, v)
__device__ float d_f[BDIM * NF * NF];         // fine grid (b, u, v)

// ---------------------------------------------------------------------------
// Kernel 0: build the c-table.
// c[d] = (1/128) * ( D0 + sum_{k=1..63} 2*Dk*cos(2*pi*k*d/256) + D64*cos(pi*d/2) )
// Dk = 1 / Phi(k/256),  Phi(nu) = int_{-4}^{4} phi(t) cos(2*pi*nu*t) dt
// phi(t) = exp(BETA*(sqrt(1-(t/4)^2)-1))
// ---------------------------------------------------------------------------
__global__ void build_ctab_kernel() {
    __shared__ float sD[65];
    int tid = threadIdx.x;
    if (tid <= 64) {
        const int NQ = 512;
        float h = 8.0f / NQ;
        float acc = 0.0f;
        for (int i = 0; i < NQ; i++) {
            float t = -4.0f + (i + 0.5f) * h;
            float z = t * 0.25f;
            float phi = expf(BETA * (sqrtf(fmaxf(1.0f - z * z, 0.0f)) - 1.0f));
            // cos(2*pi*(k/256)*t) = cos(pi * (k*t/128))
            acc += phi * cospif((float)tid * t * (1.0f / 128.0f));
        }
        sD[tid] = 1.0f / (acc * h);
    }
    __syncthreads();
    int d = tid;  // 0..255
    float s = sD[0];
    #pragma unroll 8
    for (int k = 1; k < 64; k++) {
        s += 2.0f * sD[k] * cospif((float)(k * d) * (1.0f / 128.0f));
    }
    s += sD[64] * cospif(0.5f * (float)d);
    d_ctab[d] = s * (1.0f / 128.0f);
}

// ---------------------------------------------------------------------------
// Kernel 1: corner coefficient F[b,64,64] = sum psi * (-1)^(m+n)
// ---------------------------------------------------------------------------
__global__ void corner_kernel(const float* __restrict__ psi) {
    __shared__ float red[256];
    int b = blockIdx.x;
    const float* p = psi + b * (KDIM * KDIM);
    float acc = 0.0f;
    for (int idx = threadIdx.x; idx < KDIM * KDIM; idx += 256) {
        float v = p[idx];
        int par = ((idx >> 7) ^ idx) & 1;   // (m+n) & 1
        acc += par ? -v : v;
    }
    red[threadIdx.x] = acc;
    __syncthreads();
    for (int s = 128; s > 0; s >>= 1) {
        if (threadIdx.x < s) red[threadIdx.x] += red[threadIdx.x + s];
        __syncthreads();
    }
    if (threadIdx.x == 0) d_corner[b] = red[0];
}

// ---------------------------------------------------------------------------
// Kernel 2 (stage 1): g[b,m,v] = sum_n psi[b,m,n] * c[(v - 2n) mod 256]
// Tiled 64x64, 256 threads, 4x4 micro-tile per thread.
// grid: (v_tiles=4, m_tiles=2, B=16)
// ---------------------------------------------------------------------------
__global__ void stage1_kernel(const float* __restrict__ psi) {
    __shared__ float cs[256];
    __shared__ float As[16][68];   // As[nk][mi] = psi[m0+mi][n0+nk]
    __shared__ float Bs[16][68];   // Bs[nk][vj] = c[(v0+vj - 2(n0+nk)) & 255]
    int b  = blockIdx.z;
    int m0 = blockIdx.y * 64;
    int v0 = blockIdx.x * 64;
    int tid = threadIdx.x;
    cs[tid] = d_ctab[tid];
    int tx = tid & 15, ty = tid >> 4;
    float acc[4][4] = {};
    const float* P = psi + b * (KDIM * KDIM);

    for (int n0 = 0; n0 < KDIM; n0 += 16) {
        __syncthreads();
        #pragma unroll
        for (int i = 0; i < 4; i++) {
            int e = tid + i * 256;
            int nk = e & 15, r = e >> 4;   // r in 0..63
            As[nk][r] = P[(m0 + r) * KDIM + n0 + nk];
            Bs[nk][r] = cs[(v0 + r - 2 * (n0 + nk)) & 255];
        }
        __syncthreads();
        #pragma unroll
        for (int nk = 0; nk < 16; nk++) {
            float4 a  = *(const float4*)&As[nk][ty * 4];
            float4 bb = *(const float4*)&Bs[nk][tx * 4];
            float av[4] = {a.x, a.y, a.z, a.w};
            float bv[4] = {bb.x, bb.y, bb.z, bb.w};
            #pragma unroll
            for (int i = 0; i < 4; i++)
                #pragma unroll
                for (int j = 0; j < 4; j++)
                    acc[i][j] = fmaf(av[i], bv[j], acc[i][j]);
        }
    }
    float* G = d_g + b * (KDIM * NF);
    #pragma unroll
    for (int i = 0; i < 4; i++) {
        float4 o = make_float4(acc[i][0], acc[i][1], acc[i][2], acc[i][3]);
        *(float4*)&G[(m0 + ty * 4 + i) * NF + v0 + tx * 4] = o;
    }
}

// ---------------------------------------------------------------------------
// Kernel 3 (stage 2): f[b,u,v] = sum_m c[(u - 2m) mod 256] * g[b,m,v]
// grid: (v_tiles=4, u_tiles=4, B=16)
// ---------------------------------------------------------------------------
__global__ void stage2_kernel() {
    __shared__ float cs[256];
    __shared__ float As[16][68];   // As[mk][ui] = c[(u0+ui - 2(m0+mk)) & 255]
    __shared__ float Bs[16][68];   // Bs[mk][vj] = g[m0+mk][v0+vj]
    int b  = blockIdx.z;
    int u0 = blockIdx.y * 64;
    int v0 = blockIdx.x * 64;
    int tid = threadIdx.x;
    cs[tid] = d_ctab[tid];
    int tx = tid & 15, ty = tid >> 4;
    float acc[4][4] = {};
    const float* G = d_g + b * (KDIM * NF);

    for (int m0 = 0; m0 < KDIM; m0 += 16) {
        __syncthreads();
        #pragma unroll
        for (int i = 0; i < 4; i++) {
            int e = tid + i * 256;
            int r = e & 63, mk = e >> 6;   // mk in 0..15
            As[mk][r] = cs[(u0 + r - 2 * (m0 + mk)) & 255];
            Bs[mk][r] = G[(m0 + mk) * NF + v0 + r];
        }
        __syncthreads();
        #pragma unroll
        for (int mk = 0; mk < 16; mk++) {
            float4 a  = *(const float4*)&As[mk][ty * 4];
            float4 bb = *(const float4*)&Bs[mk][tx * 4];
            float av[4] = {a.x, a.y, a.z, a.w};
            float bv[4] = {bb.x, bb.y, bb.z, bb.w};
            #pragma unroll
            for (int i = 0; i < 4; i++)
                #pragma unroll
                for (int j = 0; j < 4; j++)
                    acc[i][j] = fmaf(av[i], bv[j], acc[i][j]);
        }
    }
    float* F = d_f + b * (NF * NF);
    #pragma unroll
    for (int i = 0; i < 4; i++) {
        float4 o = make_float4(acc[i][0], acc[i][1], acc[i][2], acc[i][3]);
        *(float4*)&F[(u0 + ty * 4 + i) * NF + v0 + tx * 4] = o;
    }
}

// ---------------------------------------------------------------------------
// Kernel 4: interpolation, one warp per point.
// out[p] = sum_{8x8 window} wy[a]*wx[c]*f[b, (iy0-3+a)&255, (ix0-3+c)&255]
//          - corner[b]/K^2 * sin(64x)*sin(64y)
// ---------------------------------------------------------------------------
__global__ void interp_kernel(const float* __restrict__ x0,
                              const float* __restrict__ y0,
                              float* __restrict__ out) {
    int lane   = threadIdx.x & 31;
    int warp   = blockIdx.x * (blockDim.x >> 5) + (threadIdx.x >> 5);
    int nwarps = gridDim.x * (blockDim.x >> 5);

    for (int p = warp; p < BDIM * LDIM; p += nwarps) {
        int b = p >> 13;                       // / LDIM
        float x = x0[p], y = y0[p];
        float txr = x * (128.0f / PI_F);       // grid coords in [-128, 128]
        float tyr = y * (128.0f / PI_F);
        float tx = txr + 256.0f;
        float ty = tyr + 256.0f;
        float fx = floorf(tx), fy = floorf(ty);
        int ix0 = (int)fx, iy0 = (int)fy;
        float dx = tx - fx, dy = ty - fy;

        // lanes 0..7 compute wy[a], lanes 8..15 compute wx[c]
        int li = lane & 7;
        float dd = (lane < 8) ? dy : dx;
        float z = (dd + 3.0f - (float)li) * 0.25f;
        float wv = expf(BETA * (sqrtf(fmaxf(1.0f - z * z, 0.0f)) - 1.0f));

        const float* F = d_f + (b << 16);
        float s = 0.0f;
        #pragma unroll
        for (int h = 0; h < 2; h++) {
            int e = lane + 32 * h;
            int a = e >> 3, c = e & 7;
            int row = (iy0 - 3 + a) & 255;
            int col = (ix0 - 3 + c) & 255;
            float v = __ldg(&F[(row << 8) + col]);
            float wy = __shfl_sync(0xffffffffu, wv, a);
            float wx = __shfl_sync(0xffffffffu, wv, 8 + c);
            s += v * wy * wx;
        }
        #pragma unroll
        for (int o = 16; o; o >>= 1)
            s += __shfl_xor_sync(0xffffffffu, s, o);

        if (lane == 0) {
            // exact correction for the split Nyquist corner mode:
            // sin(64x) = sin(pi * txr / 2)
            float corr = d_corner[b] * (1.0f / 16384.0f) *
                         sinpif(0.5f * txr) * sinpif(0.5f * tyr);
            out[p] = s - corr;
        }
    }
}

// ---------------------------------------------------------------------------
extern "C" void kernel_launch(void* const* d_in, const int* in_sizes, int n_in,
                              void* d_out, int out_size) {
    const float* x0  = (const float*)d_in[0];
    const float* y0  = (const float*)d_in[1];
    const float* psi = (const float*)d_in[2];
    float* out = (float*)d_out;

    build_ctab_kernel<<<1, 256>>>();
    corner_kernel<<<BDIM, 256>>>(psi);
    stage1_kernel<<<dim3(4, 2, BDIM), 256>>>(psi);
    stage2_kernel<<<dim3(4, 4, BDIM), 256>>>();
    interp_kernel<<<2048, 256>>>(x0, y0, out);
}

// round 2
// speedup vs baseline: 2.3526x; 2.3526x over previous
#include <cuda_runtime.h>
#include <math.h>

// Problem constants
#define KDIM 128
#define BDIM 16
#define LDIM 8192
#define NF   256            // fine grid (oversampling sigma = 2)
#define WHALF 2.5f          // window half-width (w = 5)
#define BETA  11.5f         // ES beta = 2.30 * w
#define PI_F 3.14159265358979f

#define FSTRIDE 272         // fine-grid row stride (256 + 8 halo + 8 pad)
#define FBATCH  (NF * FSTRIDE)   // 69632 floats per batch
#define LUTN 1600           // window LUT entries, step 1/512, domain [0, 3.125)

// Scratch (device globals; no cudaMalloc allowed)
__device__ float  d_phi[65];                 // quadrature integrals Phi_k
__device__ float  d_ctab[256];               // combined deconv+IDFT table (incl. 1/K)
__device__ float  d_corner[BDIM];            // F[64,64] per batch
__device__ float2 d_wlut[LUTN];              // window LUT: (value, delta)
__device__ float  d_g[BDIM * KDIM * NF];     // stage-1 intermediate (b, m, v)
__device__ float  d_f[BDIM * FBATCH];        // fine grid with x halo

__device__ __forceinline__ float es_win(float dist) {
    float z = dist * (1.0f / WHALF);
    float t = 1.0f - z * z;
    if (t <= 0.0f) return 0.0f;
    return expf(BETA * (sqrtf(t) - 1.0f));
}

// ---------------------------------------------------------------------------
// Prep kernel, grid 88 x 256:
//  blocks 0..64   : Phi_k quadrature (one k per block)
//  blocks 65..71  : window LUT
//  blocks 72..87  : corner coefficient per batch
// ---------------------------------------------------------------------------
__global__ void prep_kernel(const float* __restrict__ psi) {
    int bid = blockIdx.x;
    int tid = threadIdx.x;

    if (bid < 65) {
        // Phi_k = int_{-2.5}^{2.5} W(t) cos(2*pi*(k/256)*t) dt, midpoint NQ=512
        __shared__ float red[256];
        const int NQ = 512;
        float h = (2.0f * WHALF) / NQ;
        float k = (float)bid;
        float acc = 0.0f;
        #pragma unroll
        for (int r = 0; r < 2; r++) {
            int i = tid + r * 256;
            float t = -WHALF + (i + 0.5f) * h;
            // cos(2*pi*(k/256)*t) = cospi(k*t/128)
            acc += es_win(fabsf(t)) * cospif(k * t * (1.0f / 128.0f));
        }
        red[tid] = acc;
        __syncthreads();
        for (int s = 128; s > 0; s >>= 1) {
            if (tid < s) red[tid] += red[tid + s];
            __syncthreads();
        }
        if (tid == 0) d_phi[bid] = red[0] * h;
    } else if (bid < 72) {
        int i = (bid - 65) * 256 + tid;
        if (i < LUTN) {
            float h = 1.0f / 512.0f;
            float v0 = es_win((float)i * h);
            float v1 = es_win((float)(i + 1) * h);
            d_wlut[i] = make_float2(v0, v1 - v0);
        }
    } else {
        // corner: F[b,64,64] = sum psi * (-1)^(m+n)
        __shared__ float red[256];
        int b = bid - 72;
        const float* p = psi + b * (KDIM * KDIM);
        float acc = 0.0f;
        for (int idx = tid; idx < KDIM * KDIM; idx += 256) {
            float v = p[idx];
            int par = ((idx >> 7) ^ idx) & 1;
            acc += par ? -v : v;
        }
        red[tid] = acc;
        __syncthreads();
        for (int s = 128; s > 0; s >>= 1) {
            if (tid < s) red[tid] += red[tid + s];
            __syncthreads();
        }
        if (tid == 0) d_corner[b] = red[0];
    }
}

// ---------------------------------------------------------------------------
// c-table combine: c[d] = (1/128)(D0 + sum 2*Dk*cos(2 pi k d/256) + D64 cos(pi d/2))
// Dk = 1/Phi_k
// ---------------------------------------------------------------------------
__global__ void ctab_kernel() {
    __shared__ float sD[65];
    int tid = threadIdx.x;
    if (tid < 65) sD[tid] = 1.0f / d_phi[tid];
    __syncthreads();
    int d = tid;
    float s = sD[0];
    #pragma unroll 8
    for (int k = 1; k < 64; k++) {
        s += 2.0f * sD[k] * cospif((float)(k * d) * (1.0f / 128.0f));
    }
    s += sD[64] * cospif(0.5f * (float)d);
    d_ctab[d] = s * (1.0f / 128.0f);
}

// ---------------------------------------------------------------------------
// Stage 1: g[b,m,v] = sum_n psi[b,m,n] * c[(v - 2n) mod 256]
// ---------------------------------------------------------------------------
__global__ void stage1_kernel(const float* __restrict__ psi) {
    __shared__ float cs[256];
    __shared__ float As[16][68];
    __shared__ float Bs[16][68];
    int b  = blockIdx.z;
    int m0 = blockIdx.y * 64;
    int v0 = blockIdx.x * 64;
    int tid = threadIdx.x;
    cs[tid] = d_ctab[tid];
    int tx = tid & 15, ty = tid >> 4;
    float acc[4][4] = {};
    const float* P = psi + b * (KDIM * KDIM);

    for (int n0 = 0; n0 < KDIM; n0 += 16) {
        __syncthreads();
        #pragma unroll
        for (int i = 0; i < 4; i++) {
            int e = tid + i * 256;
            int nk = e & 15, r = e >> 4;
            As[nk][r] = P[(m0 + r) * KDIM + n0 + nk];
            Bs[nk][r] = cs[(v0 + r - 2 * (n0 + nk)) & 255];
        }
        __syncthreads();
        #pragma unroll
        for (int nk = 0; nk < 16; nk++) {
            float4 a  = *(const float4*)&As[nk][ty * 4];
            float4 bb = *(const float4*)&Bs[nk][tx * 4];
            float av[4] = {a.x, a.y, a.z, a.w};
            float bv[4] = {bb.x, bb.y, bb.z, bb.w};
            #pragma unroll
            for (int i = 0; i < 4; i++)
                #pragma unroll
                for (int j = 0; j < 4; j++)
                    acc[i][j] = fmaf(av[i], bv[j], acc[i][j]);
        }
    }
    float* G = d_g + b * (KDIM * NF);
    #pragma unroll
    for (int i = 0; i < 4; i++) {
        float4 o = make_float4(acc[i][0], acc[i][1], acc[i][2], acc[i][3]);
        *(float4*)&G[(m0 + ty * 4 + i) * NF + v0 + tx * 4] = o;
    }
}

// ---------------------------------------------------------------------------
// Stage 2: f[b,u,v] = sum_m c[(u - 2m) mod 256] * g[b,m,v]
// writes padded layout (x offset +4) and fills the x halo.
// ---------------------------------------------------------------------------
__global__ void stage2_kernel() {
    __shared__ float cs[256];
    __shared__ float As[16][68];
    __shared__ float Bs[16][68];
    int b  = blockIdx.z;
    int u0 = blockIdx.y * 64;
    int v0 = blockIdx.x * 64;
    int tid = threadIdx.x;
    cs[tid] = d_ctab[tid];
    int tx = tid & 15, ty = tid >> 4;
    float acc[4][4] = {};
    const float* G = d_g + b * (KDIM * NF);

    for (int m0 = 0; m0 < KDIM; m0 += 16) {
        __syncthreads();
        #pragma unroll
        for (int i = 0; i < 4; i++) {
            int e = tid + i * 256;
            int r = e & 63, mk = e >> 6;
            As[mk][r] = cs[(u0 + r - 2 * (m0 + mk)) & 255];
            Bs[mk][r] = G[(m0 + mk) * NF + v0 + r];
        }
        __syncthreads();
        #pragma unroll
        for (int mk = 0; mk < 16; mk++) {
            float4 a  = *(const float4*)&As[mk][ty * 4];
            float4 bb = *(const float4*)&Bs[mk][tx * 4];
            float av[4] = {a.x, a.y, a.z, a.w};
            float bv[4] = {bb.x, bb.y, bb.z, bb.w};
            #pragma unroll
            for (int i = 0; i < 4; i++)
                #pragma unroll
                for (int j = 0; j < 4; j++)
                    acc[i][j] = fmaf(av[i], bv[j], acc[i][j]);
        }
    }
    float* F = d_f + b * FBATCH;
    int col = v0 + tx * 4;
    #pragma unroll
    for (int i = 0; i < 4; i++) {
        int row = u0 + ty * 4 + i;
        float4 o = make_float4(acc[i][0], acc[i][1], acc[i][2], acc[i][3]);
        *(float4*)&F[row * FSTRIDE + col + 4] = o;
        if (col == 0)   *(float4*)&F[row * FSTRIDE + 260] = o;  // right halo = cols 0..3
        if (col == 252) *(float4*)&F[row * FSTRIDE + 0]   = o;  // left halo  = cols 252..255
    }
}

// ---------------------------------------------------------------------------
// Interpolation: one thread per point, w=5 ES window via shared LUT.
// ---------------------------------------------------------------------------
__global__ void interp_kernel(const float* __restrict__ x0,
                              const float* __restrict__ y0,
                              float* __restrict__ out) {
    __shared__ float2 slut[LUTN];
    int tid = threadIdx.x;
    for (int i = tid; i < LUTN; i += 256) slut[i] = d_wlut[i];
    __syncthreads();

    int p = blockIdx.x * 256 + tid;
    int b = p >> 13;
    float x = x0[p], y = y0[p];
    float txr = x * (128.0f / PI_F);         // for corner correction
    float tyr = y * (128.0f / PI_F);
    float tx = txr + 256.0f;                 // in [~128, ~384]
    float ty = tyr + 256.0f;
    if (tx >= 256.0f) tx -= 256.0f;          // reduce to [0, 256)
    if (ty >= 256.0f) ty -= 256.0f;

    float fx = floorf(tx), fy = floorf(ty);
    int ix0 = (int)fx, iy0 = (int)fy;
    float dx = tx - fx, dy = ty - fy;

    int ic0 = ix0 - 2 + (dx >= 0.5f);        // first of 5 support columns
    int xb  = ic0 & ~3;                      // float4-aligned base, in [-4, 252]
    int ir0 = iy0 - 2 + (dy >= 0.5f);        // first of 5 support rows

    // x weights at 8 aligned columns (3 will be zero)
    float wx[8];
    #pragma unroll
    for (int j = 0; j < 8; j++) {
        float d  = fabsf(tx - (float)(xb + j));
        float fi = d * 512.0f;
        int idx  = (int)fi;
        float fr = fi - (float)idx;
        if (idx > LUTN - 1) { idx = LUTN - 1; fr = 0.0f; }
        float2 e = slut[idx];
        wx[j] = fmaf(fr, e.y, e.x);
    }
    // y weights at 5 rows
    float wy[5];
    #pragma unroll
    for (int a = 0; a < 5; a++) {
        float d  = fabsf(ty - (float)(ir0 + a));
        float fi = d * 512.0f;
        int idx  = (int)fi;
        float fr = fi - (float)idx;
        if (idx > LUTN - 1) { idx = LUTN - 1; fr = 0.0f; }
        float2 e = slut[idx];
        wy[a] = fmaf(fr, e.y, e.x);
    }

    const float* Fb = d_f + b * FBATCH;
    float acc = 0.0f;
    #pragma unroll
    for (int a = 0; a < 5; a++) {
        int row = (ir0 + a) & 255;
        const float4* rp = (const float4*)(Fb + row * FSTRIDE + xb + 4);
        float4 A = __ldg(rp);
        float4 Bv = __ldg(rp + 1);
        float rs = wx[0] * A.x + wx[1] * A.y + wx[2] * A.z + wx[3] * A.w
                 + wx[4] * Bv.x + wx[5] * Bv.y + wx[6] * Bv.z + wx[7] * Bv.w;
        acc = fmaf(wy[a], rs, acc);
    }

    // exact correction for the split Nyquist corner mode
    float corr = d_corner[b] * (1.0f / 16384.0f) *
                 sinpif(0.5f * txr) * sinpif(0.5f * tyr);
    out[p] = acc - corr;
}

// ---------------------------------------------------------------------------
extern "C" void kernel_launch(void* const* d_in, const int* in_sizes, int n_in,
                              void* d_out, int out_size) {
    const float* x0  = (const float*)d_in[0];
    const float* y0  = (const float*)d_in[1];
    const float* psi = (const float*)d_in[2];
    float* out = (float*)d_out;

    prep_kernel<<<88, 256>>>(psi);
    ctab_kernel<<<1, 256>>>();
    stage1_kernel<<<dim3(4, 2, BDIM), 256>>>(psi);
    stage2_kernel<<<dim3(4, 4, BDIM), 256>>>();
    interp_kernel<<<512, 256>>>(x0, y0, out);
}